// round 1
// baseline (speedup 1.0000x reference)
#include <cuda_runtime.h>
#include <cuda_fp16.h>
#include <math.h>
#include <stdint.h>

// Problem constants
#define T_TOKENS 8192
#define D_DIM    1024
#define H_DIM    4096
#define R_DIM    512
#define E_NUM    8
#define SLOTS    (T_TOKENS * 2)
#define MAX_TILES 144

// ---------------- scratch (device globals; no allocation allowed) ----------
__device__ __half g_xh[T_TOKENS * D_DIM];            // x in fp16            16.8MB
__device__ __half g_W1h[E_NUM * H_DIM * D_DIM];      // W1 fp16              67MB
__device__ __half g_W2h[E_NUM * D_DIM * H_DIM];      // W2 fp16              67MB
__device__ float  g_hrouter[T_TOKENS * R_DIM];       // gelu(x@Wr1^T+br1)    16.8MB
__device__ __half g_He[SLOTS * H_DIM];               // expert hidden        134MB
__device__ float  g_Y[SLOTS * D_DIM];                // expert output        67MB
__device__ int    g_expIdx[SLOTS];
__device__ float  g_expW[SLOTS];
__device__ int    g_counts[E_NUM];
__device__ int    g_fillpos[E_NUM];
__device__ int    g_perm[SLOTS];
__device__ int    g_tileExpert[MAX_TILES];
__device__ int    g_tilePos[MAX_TILES];
__device__ int    g_tileEnd[MAX_TILES];
__device__ int    g_nTiles;

__device__ __forceinline__ float gelu_exact(float x) {
    return 0.5f * x * (1.0f + erff(x * 0.7071067811865476f));
}

// ---------------- misc small kernels ---------------------------------------
__global__ void zero_counts_kernel() {
    if (threadIdx.x < E_NUM) g_counts[threadIdx.x] = 0;
}

// fp32 -> fp16 conversion (4 elems/thread). tag: 0=x, 1=W1, 2=W2
__global__ void f2h_kernel(const float* __restrict__ src, int n4, int tag) {
    int i = blockIdx.x * blockDim.x + threadIdx.x;
    if (i >= n4) return;
    __half* dst = (tag == 0) ? g_xh : ((tag == 1) ? g_W1h : g_W2h);
    float4 v = reinterpret_cast<const float4*>(src)[i];
    __half2* d2 = reinterpret_cast<__half2*>(dst + (size_t)i * 4);
    d2[0] = __floats2half2_rn(v.x, v.y);
    d2[1] = __floats2half2_rn(v.z, v.w);
}

// ---------------- router GEMM1 (fp32, must match JAX fp32 closely) ---------
// C[8192,512] = gelu(x @ Wr1^T + br1). 128x128 tile, BK=16, 256 thr, 8x8/thr
__global__ void __launch_bounds__(256) sgemm_router(
    const float* __restrict__ A,     // x   [8192,1024]
    const float* __restrict__ B,     // Wr1 [512,1024]
    const float* __restrict__ bias)  // br1 [512]
{
    __shared__ float As[16][132];
    __shared__ float Bs[16][132];
    const int tid = threadIdx.x;
    const int m0 = blockIdx.y * 128;
    const int n0 = blockIdx.x * 128;
    const int tx = tid & 15, ty = tid >> 4;

    float acc[8][8];
#pragma unroll
    for (int i = 0; i < 8; i++)
#pragma unroll
        for (int j = 0; j < 8; j++) acc[i][j] = 0.f;

    for (int k0 = 0; k0 < 1024; k0 += 16) {
#pragma unroll
        for (int j = 0; j < 2; j++) {
            int c = tid + j * 256;
            int row = c >> 2;
            int kc = (c & 3) << 2;
            float4 av = *reinterpret_cast<const float4*>(&A[(size_t)(m0 + row) * 1024 + k0 + kc]);
            As[kc + 0][row] = av.x; As[kc + 1][row] = av.y;
            As[kc + 2][row] = av.z; As[kc + 3][row] = av.w;
            float4 bv = *reinterpret_cast<const float4*>(&B[(size_t)(n0 + row) * 1024 + k0 + kc]);
            Bs[kc + 0][row] = bv.x; Bs[kc + 1][row] = bv.y;
            Bs[kc + 2][row] = bv.z; Bs[kc + 3][row] = bv.w;
        }
        __syncthreads();
#pragma unroll
        for (int k = 0; k < 16; k++) {
            float a[8], b[8];
            *reinterpret_cast<float4*>(&a[0]) = *reinterpret_cast<const float4*>(&As[k][ty * 8]);
            *reinterpret_cast<float4*>(&a[4]) = *reinterpret_cast<const float4*>(&As[k][ty * 8 + 4]);
            *reinterpret_cast<float4*>(&b[0]) = *reinterpret_cast<const float4*>(&Bs[k][tx * 8]);
            *reinterpret_cast<float4*>(&b[4]) = *reinterpret_cast<const float4*>(&Bs[k][tx * 8 + 4]);
#pragma unroll
            for (int i = 0; i < 8; i++)
#pragma unroll
                for (int j = 0; j < 8; j++) acc[i][j] += a[i] * b[j];
        }
        __syncthreads();
    }
#pragma unroll
    for (int i = 0; i < 8; i++) {
        int row = m0 + ty * 8 + i;
#pragma unroll
        for (int j = 0; j < 8; j++) {
            int col = n0 + tx * 8 + j;
            float v = acc[i][j] + bias[col];
            g_hrouter[(size_t)row * R_DIM + col] = gelu_exact(v);
        }
    }
}

// ---------------- router stage 2: logits, softmax, top-2 -------------------
__global__ void router_topk_kernel(const float* __restrict__ Wr2,  // [8,512]
                                   const float* __restrict__ br2)  // [8]
{
    int warp = threadIdx.x >> 5;
    int lane = threadIdx.x & 31;
    int t = blockIdx.x * 8 + warp;
    const float* h = g_hrouter + (size_t)t * R_DIM;

    float acc[E_NUM];
#pragma unroll
    for (int e = 0; e < E_NUM; e++) acc[e] = 0.f;
#pragma unroll
    for (int j = 0; j < 16; j++) {
        int i = lane + 32 * j;
        float hv = h[i];
#pragma unroll
        for (int e = 0; e < E_NUM; e++) acc[e] += hv * Wr2[e * R_DIM + i];
    }
#pragma unroll
    for (int off = 16; off > 0; off >>= 1)
#pragma unroll
        for (int e = 0; e < E_NUM; e++)
            acc[e] += __shfl_xor_sync(0xffffffffu, acc[e], off);

    if (lane == 0) {
        float l[E_NUM];
#pragma unroll
        for (int e = 0; e < E_NUM; e++) l[e] = acc[e] + br2[e];
        // top-2, lower index wins ties (matches jax.lax.top_k)
        int i0 = 0; float v0 = l[0];
#pragma unroll
        for (int e = 1; e < E_NUM; e++) if (l[e] > v0) { v0 = l[e]; i0 = e; }
        int i1 = -1; float v1 = -1e30f;
#pragma unroll
        for (int e = 0; e < E_NUM; e++) if (e != i0 && l[e] > v1) { v1 = l[e]; i1 = e; }
        // softmax probs of the two winners
        float m = v0;
        float s = 0.f;
#pragma unroll
        for (int e = 0; e < E_NUM; e++) s += __expf(l[e] - m) * 0.0f + expf(l[e] - m);
        float w0 = expf(v0 - m) / s;
        float w1 = expf(v1 - m) / s;
        g_expIdx[2 * t] = i0;     g_expIdx[2 * t + 1] = i1;
        g_expW[2 * t] = w0;       g_expW[2 * t + 1] = w1;
        atomicAdd(&g_counts[i0], 1);
        atomicAdd(&g_counts[i1], 1);
    }
}

// ---------------- scan + tile map (single thread; <=136 iterations) --------
__global__ void scan_kernel() {
    int off = 0, nt = 0;
    for (int e = 0; e < E_NUM; e++) {
        int cnt = g_counts[e];
        g_fillpos[e] = off;
        int tiles = (cnt + 127) >> 7;
        for (int j = 0; j < tiles; j++) {
            g_tileExpert[nt] = e;
            g_tilePos[nt] = off + j * 128;
            g_tileEnd[nt] = off + cnt;
            nt++;
        }
        off += cnt;
    }
    g_nTiles = nt;
}

__global__ void fill_kernel() {
    int s = blockIdx.x * blockDim.x + threadIdx.x;
    if (s >= SLOTS) return;
    int e = g_expIdx[s];
    int pos = atomicAdd(&g_fillpos[e], 1);
    g_perm[pos] = s;  // order nondeterministic; per-slot values deterministic
}

// ---------------- grouped expert GEMM (fp16 mma.sync, fp32 accum) ----------
// UP:  He[slot,4096] = gelu(xh[tok] @ W1[e]^T + b1[e])   (K=1024, N=4096)
// !UP: Y [slot,1024] =      He[slot] @ W2[e]^T + b2[e]   (K=4096, N=1024)
template <bool UP>
__global__ void __launch_bounds__(256, 2) expert_gemm(const float* __restrict__ bias)
{
    constexpr int N_DIM = UP ? H_DIM : D_DIM;
    constexpr int K_DIM = UP ? D_DIM : H_DIM;
    constexpr int SHIFT = UP ? 1 : 0;

    __shared__ __half As[128 * 72];
    __shared__ __half Bs[128 * 72];
    __shared__ int sSlot[128];

    int mt = blockIdx.y;
    if (mt >= g_nTiles) return;
    const int e      = g_tileExpert[mt];
    const int pos0   = g_tilePos[mt];
    const int segEnd = g_tileEnd[mt];
    const int n0     = blockIdx.x * 128;
    const int tid    = threadIdx.x;

    if (tid < 128) {
        int p = pos0 + tid;
        sSlot[tid] = (p < segEnd) ? g_perm[p] : -1;
    }
    __syncthreads();

    const __half* Abase = UP ? g_xh : g_He;
    const __half* W     = (UP ? g_W1h : g_W2h) + (size_t)e * N_DIM * K_DIM;
    const float*  bptr  = bias + (size_t)e * N_DIM;

    const int warpId = tid >> 5;
    const int lane   = tid & 31;
    const int wm = (warpId & 1) * 64;
    const int wn = (warpId >> 1) * 32;

    float acc[4][4][4];
#pragma unroll
    for (int i = 0; i < 4; i++)
#pragma unroll
        for (int j = 0; j < 4; j++)
#pragma unroll
            for (int k = 0; k < 4; k++) acc[i][j][k] = 0.f;

    for (int k0 = 0; k0 < K_DIM; k0 += 64) {
#pragma unroll
        for (int j = 0; j < 4; j++) {
            int c = tid + j * 256;          // 0..1023
            int row = c >> 3;               // 0..127
            int kc = (c & 7) << 3;          // 0..56
            int slot = sSlot[row];
            uint4 va = make_uint4(0u, 0u, 0u, 0u);
            if (slot >= 0)
                va = *reinterpret_cast<const uint4*>(
                    Abase + (size_t)(slot >> SHIFT) * K_DIM + k0 + kc);
            *reinterpret_cast<uint4*>(&As[row * 72 + kc]) = va;
            uint4 vb = *reinterpret_cast<const uint4*>(
                W + (size_t)(n0 + row) * K_DIM + k0 + kc);
            *reinterpret_cast<uint4*>(&Bs[row * 72 + kc]) = vb;
        }
        __syncthreads();

#pragma unroll
        for (int kk = 0; kk < 64; kk += 16) {
            uint32_t af[4][4];
            uint32_t bf[4][2];
#pragma unroll
            for (int im = 0; im < 4; im++) {
                int r  = wm + im * 16 + (lane & 15);
                int kc = kk + ((lane >> 4) << 3);
                uint32_t a = (uint32_t)__cvta_generic_to_shared(&As[r * 72 + kc]);
                asm volatile(
                    "ldmatrix.sync.aligned.m8n8.x4.shared.b16 {%0,%1,%2,%3}, [%4];"
                    : "=r"(af[im][0]), "=r"(af[im][1]), "=r"(af[im][2]), "=r"(af[im][3])
                    : "r"(a));
            }
#pragma unroll
            for (int in_ = 0; in_ < 4; in_++) {
                int r  = wn + in_ * 8 + (lane & 7);
                int kc = kk + (((lane >> 3) & 1) << 3);
                uint32_t a = (uint32_t)__cvta_generic_to_shared(&Bs[r * 72 + kc]);
                asm volatile(
                    "ldmatrix.sync.aligned.m8n8.x2.shared.b16 {%0,%1}, [%2];"
                    : "=r"(bf[in_][0]), "=r"(bf[in_][1])
                    : "r"(a));
            }
#pragma unroll
            for (int im = 0; im < 4; im++)
#pragma unroll
                for (int in_ = 0; in_ < 4; in_++) {
                    asm volatile(
                        "mma.sync.aligned.m16n8k16.row.col.f32.f16.f16.f32 "
                        "{%0,%1,%2,%3}, {%4,%5,%6,%7}, {%8,%9}, {%0,%1,%2,%3};"
                        : "+f"(acc[im][in_][0]), "+f"(acc[im][in_][1]),
                          "+f"(acc[im][in_][2]), "+f"(acc[im][in_][3])
                        : "r"(af[im][0]), "r"(af[im][1]), "r"(af[im][2]), "r"(af[im][3]),
                          "r"(bf[in_][0]), "r"(bf[in_][1]));
                }
        }
        __syncthreads();
    }

    // epilogue
    const int groupID = lane >> 2;
    const int t4 = lane & 3;
#pragma unroll
    for (int im = 0; im < 4; im++) {
#pragma unroll
        for (int hf = 0; hf < 2; hf++) {
            int rl = wm + im * 16 + groupID + hf * 8;
            int slot = sSlot[rl];
            if (slot < 0) continue;
#pragma unroll
            for (int in_ = 0; in_ < 4; in_++) {
                int nc = n0 + wn + in_ * 8 + t4 * 2;
                float v0 = acc[im][in_][hf * 2 + 0] + bptr[nc];
                float v1 = acc[im][in_][hf * 2 + 1] + bptr[nc + 1];
                if (UP) {
                    v0 = gelu_exact(v0);
                    v1 = gelu_exact(v1);
                    *reinterpret_cast<__half2*>(&g_He[(size_t)slot * N_DIM + nc]) =
                        __floats2half2_rn(v0, v1);
                } else {
                    *reinterpret_cast<float2*>(&g_Y[(size_t)slot * N_DIM + nc]) =
                        make_float2(v0, v1);
                }
            }
        }
    }
}

// ---------------- combine: out = w0*Y[2t] + w1*Y[2t+1] ---------------------
__global__ void combine_kernel(float* __restrict__ out) {
    int i = blockIdx.x * blockDim.x + threadIdx.x;  // over T*D/4
    int t = i >> 8;                                 // D/4 = 256
    int c = i & 255;
    float w0 = g_expW[2 * t];
    float w1 = g_expW[2 * t + 1];
    const float4* Y4 = reinterpret_cast<const float4*>(g_Y);
    float4 y0 = Y4[(size_t)(2 * t) * 256 + c];
    float4 y1 = Y4[(size_t)(2 * t + 1) * 256 + c];
    float4 r;
    r.x = w0 * y0.x + w1 * y1.x;
    r.y = w0 * y0.y + w1 * y1.y;
    r.z = w0 * y0.z + w1 * y1.z;
    r.w = w0 * y0.w + w1 * y1.w;
    reinterpret_cast<float4*>(out)[i] = r;
}

// ---------------- launch ----------------------------------------------------
extern "C" void kernel_launch(void* const* d_in, const int* in_sizes, int n_in,
                              void* d_out, int out_size) {
    const float* x   = (const float*)d_in[0];
    const float* Wr1 = (const float*)d_in[1];
    const float* br1 = (const float*)d_in[2];
    const float* Wr2 = (const float*)d_in[3];
    const float* br2 = (const float*)d_in[4];
    // d_in[5] = W1 (converted), d_in[6] = b1, d_in[7] = W2 (converted), d_in[8] = b2
    const float* W1  = (const float*)d_in[5];
    const float* b1  = (const float*)d_in[6];
    const float* W2  = (const float*)d_in[7];
    const float* b2  = (const float*)d_in[8];
    float* out = (float*)d_out;

    zero_counts_kernel<<<1, 32>>>();

    {
        int n4 = T_TOKENS * D_DIM / 4;
        f2h_kernel<<<n4 / 256, 256>>>(x, n4, 0);
    }
    {
        int n4 = E_NUM * H_DIM * D_DIM / 4;
        f2h_kernel<<<n4 / 256, 256>>>(W1, n4, 1);
        f2h_kernel<<<n4 / 256, 256>>>(W2, n4, 2);
    }

    sgemm_router<<<dim3(R_DIM / 128, T_TOKENS / 128), 256>>>(x, Wr1, br1);
    router_topk_kernel<<<T_TOKENS / 8, 256>>>(Wr2, br2);
    scan_kernel<<<1, 1>>>();
    fill_kernel<<<SLOTS / 256, 256>>>();

    expert_gemm<true><<<dim3(H_DIM / 128, 136), 256>>>(b1);
    expert_gemm<false><<<dim3(D_DIM / 128, 136), 256>>>(b2);

    combine_kernel<<<T_TOKENS * D_DIM / 4 / 256, 256>>>(out);
}

// round 3
// speedup vs baseline: 1.8321x; 1.8321x over previous
#include <cuda_runtime.h>
#include <cuda_fp16.h>
#include <math.h>
#include <stdint.h>

// Problem constants
#define T_TOKENS 8192
#define D_DIM    1024
#define H_DIM    4096
#define R_DIM    512
#define E_NUM    8
#define SLOTS    (T_TOKENS * 2)
#define MAX_TILES 136
#define KR_DIM   3072   // router split-K: [xh|xh|xl] x [wh|wl|wh]

// ---------------- scratch (device globals; no allocation allowed) ----------
__device__ __half g_xsplit[T_TOKENS * KR_DIM];       // [xh|xh|xl]      50MB
__device__ __half g_wr1split[R_DIM * KR_DIM];        // [wh|wl|wh]*32    3MB
__device__ __half g_W1h[E_NUM * H_DIM * D_DIM];      // W1 fp16         67MB
__device__ __half g_W2h[E_NUM * D_DIM * H_DIM];      // W2 fp16         67MB
__device__ float  g_hrouter[T_TOKENS * R_DIM];       // gelu(x@Wr1^T+br1)
__device__ __half g_He[SLOTS * H_DIM];               // expert hidden  134MB
__device__ float  g_Y[SLOTS * D_DIM];                // expert output   67MB
__device__ int    g_expIdx[SLOTS];
__device__ float  g_expW[SLOTS];
__device__ int    g_counts[E_NUM];
__device__ int    g_fillpos[E_NUM];
__device__ int    g_perm[SLOTS];
__device__ int    g_tileExpert[MAX_TILES];
__device__ int    g_tilePos[MAX_TILES];
__device__ int    g_tileEnd[MAX_TILES];
__device__ int    g_nTiles;

__device__ __forceinline__ float gelu_exact(float x) {
    return 0.5f * x * (1.0f + erff(x * 0.7071067811865476f));
}

__device__ __forceinline__ uint32_t smem_to_u32(const void* p) {
    uint32_t a;
    asm("{ .reg .u64 t; cvta.to.shared.u64 t, %1; cvt.u32.u64 %0, t; }" : "=r"(a) : "l"(p));
    return a;
}
#define CP_ASYNC16(dst, src, sz) \
    asm volatile("cp.async.cg.shared.global [%0], [%1], 16, %2;" \
                 :: "r"(dst), "l"(src), "r"(sz))
#define CP_COMMIT() asm volatile("cp.async.commit_group;" ::: "memory")
#define CP_WAIT3()  asm volatile("cp.async.wait_group 3;" ::: "memory")

// ---------------- misc small kernels ---------------------------------------
__global__ void zero_counts_kernel() {
    if (threadIdx.x < E_NUM) g_counts[threadIdx.x] = 0;
}

// x -> [xh | xh | xl]  (row stride 3072)
__global__ void xsplit_kernel(const float* __restrict__ x) {
    int i = blockIdx.x * blockDim.x + threadIdx.x;    // over T*D/4
    int t = i >> 8;                                   // D/4 = 256
    int c4 = (i & 255) * 4;
    float4 v = reinterpret_cast<const float4*>(x)[i];
    __half h[4], l[4];
    float vv[4] = {v.x, v.y, v.z, v.w};
#pragma unroll
    for (int q = 0; q < 4; q++) {
        h[q] = __float2half_rn(vv[q]);
        l[q] = __float2half_rn(vv[q] - __half2float(h[q]));
    }
    __half* row = g_xsplit + (size_t)t * KR_DIM + c4;
    __half2 h01 = __halves2half2(h[0], h[1]), h23 = __halves2half2(h[2], h[3]);
    __half2 l01 = __halves2half2(l[0], l[1]), l23 = __halves2half2(l[2], l[3]);
    ((__half2*)(row))[0] = h01;        ((__half2*)(row))[1] = h23;
    ((__half2*)(row + 1024))[0] = h01; ((__half2*)(row + 1024))[1] = h23;
    ((__half2*)(row + 2048))[0] = l01; ((__half2*)(row + 2048))[1] = l23;
}

// Wr1*32 -> [wh | wl | wh]  (row stride 3072)
__global__ void wsplit_kernel(const float* __restrict__ w) {
    int i = blockIdx.x * blockDim.x + threadIdx.x;    // over R*D/4
    int r = i >> 8;
    int c4 = (i & 255) * 4;
    float4 v = reinterpret_cast<const float4*>(w)[i];
    float vv[4] = {v.x * 32.f, v.y * 32.f, v.z * 32.f, v.w * 32.f};
    __half h[4], l[4];
#pragma unroll
    for (int q = 0; q < 4; q++) {
        h[q] = __float2half_rn(vv[q]);
        l[q] = __float2half_rn(vv[q] - __half2float(h[q]));
    }
    __half* row = g_wr1split + (size_t)r * KR_DIM + c4;
    __half2 h01 = __halves2half2(h[0], h[1]), h23 = __halves2half2(h[2], h[3]);
    __half2 l01 = __halves2half2(l[0], l[1]), l23 = __halves2half2(l[2], l[3]);
    ((__half2*)(row))[0] = h01;        ((__half2*)(row))[1] = h23;
    ((__half2*)(row + 1024))[0] = l01; ((__half2*)(row + 1024))[1] = l23;
    ((__half2*)(row + 2048))[0] = h01; ((__half2*)(row + 2048))[1] = h23;
}

// fp32 -> fp16 conversion (4 elems/thread). tag: 1=W1, 2=W2
__global__ void f2h_kernel(const float* __restrict__ src, int n4, int tag) {
    int i = blockIdx.x * blockDim.x + threadIdx.x;
    if (i >= n4) return;
    __half* dst = (tag == 1) ? g_W1h : g_W2h;
    float4 v = reinterpret_cast<const float4*>(src)[i];
    __half2* d2 = reinterpret_cast<__half2*>(dst + (size_t)i * 4);
    d2[0] = __floats2half2_rn(v.x, v.y);
    d2[1] = __floats2half2_rn(v.z, v.w);
}

// ---------------- unified HMMA GEMM -----------------------------------------
// MODE 0: router  h = gelu((1/32)*A'B'^T + br1) -> g_hrouter fp32, M dense
// MODE 1: UP      He = gelu(xh@W1[e]^T + b1[e]) fp16, gathered (token=slot>>1)
// MODE 2: DOWN    Y  = He@W2[e]^T + b2[e] fp32, gathered (slot)
// Tile M=128, N=256, K-chunk 64 (128B rows), 4-stage cp.async, 512 threads.
#define OFF_SLOT   0
#define OFF_STAGE  1024
#define STAGE_BYTES 49152           // A 16KB + B 32KB
#define NSTAGE 4
#define SMEM_TOTAL (OFF_STAGE + NSTAGE * STAGE_BYTES)

template <int MODE>
__global__ void __launch_bounds__(512, 1) moe_gemm_kernel(const float* __restrict__ bias_in)
{
    constexpr int K_DIM = (MODE == 0) ? KR_DIM : (MODE == 1 ? 1024 : 4096);
    constexpr int A_STRIDE = (MODE == 2) ? 4096 : KR_DIM;
    constexpr int NITER = K_DIM / 64;

    extern __shared__ char smem[];
    const uint32_t sb = smem_to_u32(smem);
    int* sSlot = (int*)(smem + OFF_SLOT);
    const int tid = threadIdx.x;
    const int wid = tid >> 5;
    const int lane = tid & 31;
    const int n0 = blockIdx.x * 256;

    int m0 = 0, eIdx = 0;
    if (MODE == 0) {
        m0 = blockIdx.y * 128;
    } else {
        int mt = blockIdx.y;
        if (mt >= g_nTiles) return;
        eIdx = g_tileExpert[mt];
        int pos0 = g_tilePos[mt], segEnd = g_tileEnd[mt];
        if (tid < 128) {
            int p = pos0 + tid;
            sSlot[tid] = (p < segEnd) ? g_perm[p] : -1;
        }
    }
    __syncthreads();

    const __half* Abase = (MODE == 2) ? g_He : g_xsplit;
    const __half* Bbase;
    const float* bptr;
    if (MODE == 0)      { Bbase = g_wr1split;                              bptr = bias_in; }
    else if (MODE == 1) { Bbase = g_W1h + (size_t)eIdx * (H_DIM * D_DIM);  bptr = bias_in + eIdx * H_DIM; }
    else                { Bbase = g_W2h + (size_t)eIdx * (D_DIM * H_DIM);  bptr = bias_in + eIdx * D_DIM; }

    // ---- stage loader (A: 128x128B gathered; B: 256x128B) ----
    auto load_stage = [&](int it) {
        const uint32_t so = sb + OFF_STAGE + (uint32_t)(it & 3) * STAGE_BYTES;
        const int kb = it * 128;  // bytes along K
#pragma unroll
        for (int j = 0; j < 2; j++) {
            int c = tid + j * 512;          // 0..1023
            int r = c >> 3;                 // 0..127
            int kc = (c & 7) << 4;          // 0..112
            uint32_t dst = so + (uint32_t)(r * 128 + (kc ^ ((r & 7) << 4)));
            uint32_t sz = 16;
            int arow = 0;
            if (MODE == 0) arow = m0 + r;
            else {
                int slot = sSlot[r];
                if (slot < 0) sz = 0;
                else arow = (MODE == 1) ? (slot >> 1) : slot;
            }
            const char* src = (const char*)(Abase + (size_t)arow * A_STRIDE) + kb + kc;
            CP_ASYNC16(dst, src, sz);
        }
#pragma unroll
        for (int j = 0; j < 4; j++) {
            int c = tid + j * 512;          // 0..2047
            int r = c >> 3;                 // 0..255
            int kc = (c & 7) << 4;
            uint32_t dst = so + 16384u + (uint32_t)(r * 128 + (kc ^ ((r & 7) << 4)));
            const char* src = (const char*)(Bbase + (size_t)(n0 + r) * K_DIM) + kb + kc;
            CP_ASYNC16(dst, src, 16u);
        }
    };

    // warp grid: 4 (M) x 4 (N); warp tile 32x64
    const int wm = (wid & 3) * 32;
    const int wn = (wid >> 2) * 64;

    float acc[2][8][4];
#pragma unroll
    for (int i = 0; i < 2; i++)
#pragma unroll
        for (int j = 0; j < 8; j++)
#pragma unroll
            for (int k = 0; k < 4; k++) acc[i][j][k] = 0.f;

    // prologue: fill 3 stages
#pragma unroll
    for (int p = 0; p < 3; p++) {
        load_stage(p);
        CP_COMMIT();
    }

    for (int it = 0; it < NITER; ++it) {
        if (it + 3 < NITER) load_stage(it + 3);
        CP_COMMIT();                  // one group per iter (possibly empty)
        CP_WAIT3();
        __syncthreads();

        const uint32_t aOff = sb + OFF_STAGE + (uint32_t)(it & 3) * STAGE_BYTES;
        const uint32_t bOff = aOff + 16384u;

#pragma unroll
        for (int ks = 0; ks < 4; ks++) {
            const int kb32 = ks * 32;
            uint32_t af[2][4];
#pragma unroll
            for (int mf = 0; mf < 2; mf++) {
                int r = wm + mf * 16 + (lane & 15);
                int col = kb32 + ((lane >> 4) << 4);
                uint32_t a = aOff + (uint32_t)(r * 128 + (col ^ ((r & 7) << 4)));
                asm volatile(
                    "ldmatrix.sync.aligned.m8n8.x4.shared.b16 {%0,%1,%2,%3}, [%4];"
                    : "=r"(af[mf][0]), "=r"(af[mf][1]), "=r"(af[mf][2]), "=r"(af[mf][3])
                    : "r"(a));
            }
            uint32_t bf[8][2];
#pragma unroll
            for (int np = 0; np < 4; np++) {
                int r = wn + np * 16 + ((lane >> 4) << 3) + (lane & 7);
                int col = kb32 + ((lane >> 3) & 1) * 16;
                uint32_t a = bOff + (uint32_t)(r * 128 + (col ^ ((r & 7) << 4)));
                asm volatile(
                    "ldmatrix.sync.aligned.m8n8.x4.shared.b16 {%0,%1,%2,%3}, [%4];"
                    : "=r"(bf[2 * np][0]), "=r"(bf[2 * np][1]),
                      "=r"(bf[2 * np + 1][0]), "=r"(bf[2 * np + 1][1])
                    : "r"(a));
            }
#pragma unroll
            for (int mf = 0; mf < 2; mf++)
#pragma unroll
                for (int nf = 0; nf < 8; nf++) {
                    asm volatile(
                        "mma.sync.aligned.m16n8k16.row.col.f32.f16.f16.f32 "
                        "{%0,%1,%2,%3}, {%4,%5,%6,%7}, {%8,%9}, {%0,%1,%2,%3};"
                        : "+f"(acc[mf][nf][0]), "+f"(acc[mf][nf][1]),
                          "+f"(acc[mf][nf][2]), "+f"(acc[mf][nf][3])
                        : "r"(af[mf][0]), "r"(af[mf][1]), "r"(af[mf][2]), "r"(af[mf][3]),
                          "r"(bf[nf][0]), "r"(bf[nf][1]));
                }
        }
        __syncthreads();
    }

    // ---- epilogue ----
    const int lr = lane >> 2;
    const int lc = (lane & 3) * 2;
#pragma unroll
    for (int mf = 0; mf < 2; mf++) {
#pragma unroll
        for (int h = 0; h < 2; h++) {
            int rl = wm + mf * 16 + lr + h * 8;
            int orow;
            if (MODE == 0) orow = m0 + rl;
            else {
                int slot = sSlot[rl];
                if (slot < 0) continue;
                orow = slot;
            }
#pragma unroll
            for (int nf = 0; nf < 8; nf++) {
                int col = n0 + wn + nf * 8 + lc;
                float v0 = acc[mf][nf][h * 2 + 0];
                float v1 = acc[mf][nf][h * 2 + 1];
                if (MODE == 0) {
                    v0 = gelu_exact(v0 * 0.03125f + bptr[col]);
                    v1 = gelu_exact(v1 * 0.03125f + bptr[col + 1]);
                    *reinterpret_cast<float2*>(&g_hrouter[(size_t)orow * R_DIM + col]) =
                        make_float2(v0, v1);
                } else if (MODE == 1) {
                    v0 = gelu_exact(v0 + bptr[col]);
                    v1 = gelu_exact(v1 + bptr[col + 1]);
                    *reinterpret_cast<__half2*>(&g_He[(size_t)orow * H_DIM + col]) =
                        __floats2half2_rn(v0, v1);
                } else {
                    *reinterpret_cast<float2*>(&g_Y[(size_t)orow * D_DIM + col]) =
                        make_float2(v0 + bptr[col], v1 + bptr[col + 1]);
                }
            }
        }
    }
}

// ---------------- router stage 2: logits, softmax, top-2 -------------------
__global__ void router_topk_kernel(const float* __restrict__ Wr2,  // [8,512]
                                   const float* __restrict__ br2)  // [8]
{
    int warp = threadIdx.x >> 5;
    int lane = threadIdx.x & 31;
    int t = blockIdx.x * 8 + warp;
    const float* h = g_hrouter + (size_t)t * R_DIM;

    float acc[E_NUM];
#pragma unroll
    for (int e = 0; e < E_NUM; e++) acc[e] = 0.f;
#pragma unroll
    for (int j = 0; j < 16; j++) {
        int i = lane + 32 * j;
        float hv = h[i];
#pragma unroll
        for (int e = 0; e < E_NUM; e++) acc[e] += hv * Wr2[e * R_DIM + i];
    }
#pragma unroll
    for (int off = 16; off > 0; off >>= 1)
#pragma unroll
        for (int e = 0; e < E_NUM; e++)
            acc[e] += __shfl_xor_sync(0xffffffffu, acc[e], off);

    if (lane == 0) {
        float l[E_NUM];
#pragma unroll
        for (int e = 0; e < E_NUM; e++) l[e] = acc[e] + br2[e];
        int i0 = 0; float v0 = l[0];
#pragma unroll
        for (int e = 1; e < E_NUM; e++) if (l[e] > v0) { v0 = l[e]; i0 = e; }
        int i1 = -1; float v1 = -1e30f;
#pragma unroll
        for (int e = 0; e < E_NUM; e++) if (e != i0 && l[e] > v1) { v1 = l[e]; i1 = e; }
        float m = v0;
        float s = 0.f;
#pragma unroll
        for (int e = 0; e < E_NUM; e++) s += expf(l[e] - m);
        float w0 = expf(v0 - m) / s;
        float w1 = expf(v1 - m) / s;
        g_expIdx[2 * t] = i0;     g_expIdx[2 * t + 1] = i1;
        g_expW[2 * t] = w0;       g_expW[2 * t + 1] = w1;
        atomicAdd(&g_counts[i0], 1);
        atomicAdd(&g_counts[i1], 1);
    }
}

// ---------------- scan + tile map (single thread) ---------------------------
__global__ void scan_kernel() {
    int off = 0, nt = 0;
    for (int e = 0; e < E_NUM; e++) {
        int cnt = g_counts[e];
        g_fillpos[e] = off;
        int tiles = (cnt + 127) >> 7;
        for (int j = 0; j < tiles; j++) {
            g_tileExpert[nt] = e;
            g_tilePos[nt] = off + j * 128;
            g_tileEnd[nt] = off + cnt;
            nt++;
        }
        off += cnt;
    }
    g_nTiles = nt;
}

__global__ void fill_kernel() {
    int s = blockIdx.x * blockDim.x + threadIdx.x;
    if (s >= SLOTS) return;
    int e = g_expIdx[s];
    int pos = atomicAdd(&g_fillpos[e], 1);
    g_perm[pos] = s;
}

// ---------------- combine: out = w0*Y[2t] + w1*Y[2t+1] ---------------------
__global__ void combine_kernel(float* __restrict__ out) {
    int i = blockIdx.x * blockDim.x + threadIdx.x;  // over T*D/4
    int t = i >> 8;
    int c = i & 255;
    float w0 = g_expW[2 * t];
    float w1 = g_expW[2 * t + 1];
    const float4* Y4 = reinterpret_cast<const float4*>(g_Y);
    float4 y0 = Y4[(size_t)(2 * t) * 256 + c];
    float4 y1 = Y4[(size_t)(2 * t + 1) * 256 + c];
    float4 r;
    r.x = w0 * y0.x + w1 * y1.x;
    r.y = w0 * y0.y + w1 * y1.y;
    r.z = w0 * y0.z + w1 * y1.z;
    r.w = w0 * y0.w + w1 * y1.w;
    reinterpret_cast<float4*>(out)[i] = r;
}

// ---------------- launch ----------------------------------------------------
extern "C" void kernel_launch(void* const* d_in, const int* in_sizes, int n_in,
                              void* d_out, int out_size) {
    const float* x   = (const float*)d_in[0];
    const float* Wr1 = (const float*)d_in[1];
    const float* br1 = (const float*)d_in[2];
    const float* Wr2 = (const float*)d_in[3];
    const float* br2 = (const float*)d_in[4];
    const float* W1  = (const float*)d_in[5];
    const float* b1  = (const float*)d_in[6];
    const float* W2  = (const float*)d_in[7];
    const float* b2  = (const float*)d_in[8];
    float* out = (float*)d_out;

    cudaFuncSetAttribute(moe_gemm_kernel<0>, cudaFuncAttributeMaxDynamicSharedMemorySize, SMEM_TOTAL);
    cudaFuncSetAttribute(moe_gemm_kernel<1>, cudaFuncAttributeMaxDynamicSharedMemorySize, SMEM_TOTAL);
    cudaFuncSetAttribute(moe_gemm_kernel<2>, cudaFuncAttributeMaxDynamicSharedMemorySize, SMEM_TOTAL);

    zero_counts_kernel<<<1, 32>>>();

    xsplit_kernel<<<(T_TOKENS * D_DIM / 4) / 256, 256>>>(x);
    wsplit_kernel<<<(R_DIM * D_DIM / 4) / 256, 256>>>(Wr1);
    {
        int n4 = E_NUM * H_DIM * D_DIM / 4;
        f2h_kernel<<<n4 / 256, 256>>>(W1, n4, 1);
        f2h_kernel<<<n4 / 256, 256>>>(W2, n4, 2);
    }

    // Router GEMM (exact fp16-split, K=3072): grid (512/256, 8192/128)
    moe_gemm_kernel<0><<<dim3(2, 64), 512, SMEM_TOTAL>>>(br1);
    router_topk_kernel<<<T_TOKENS / 8, 256>>>(Wr2, br2);
    scan_kernel<<<1, 1>>>();
    fill_kernel<<<SLOTS / 256, 256>>>();

    // Expert GEMMs (grouped)
    moe_gemm_kernel<1><<<dim3(H_DIM / 256, MAX_TILES), 512, SMEM_TOTAL>>>(b1);
    moe_gemm_kernel<2><<<dim3(D_DIM / 256, MAX_TILES), 512, SMEM_TOTAL>>>(b2);

    combine_kernel<<<T_TOKENS * D_DIM / 4 / 256, 256>>>(out);
}

// round 4
// speedup vs baseline: 1.9382x; 1.0579x over previous
#include <cuda_runtime.h>
#include <cuda_fp16.h>
#include <math.h>
#include <stdint.h>

// Problem constants
#define T_TOKENS 8192
#define D_DIM    1024
#define H_DIM    4096
#define R_DIM    512
#define E_NUM    8
#define SLOTS    (T_TOKENS * 2)
#define MAX_TILES 136
#define KR_DIM   3072   // router split-K: [xh|xh|xl] x [wh|wl|wh]

// ---------------- scratch (device globals; no allocation allowed) ----------
__device__ __half g_xsplit[T_TOKENS * KR_DIM];       // [xh|xh|xl]      50MB
__device__ __half g_wr1split[R_DIM * KR_DIM];        // [wh|wl|wh]*32    3MB
__device__ __half g_W1h[E_NUM * H_DIM * D_DIM];      // W1 fp16         67MB
__device__ __half g_W2h[E_NUM * D_DIM * H_DIM];      // W2 fp16         67MB
__device__ float  g_hrouter[T_TOKENS * R_DIM];       // gelu(x@Wr1^T+br1)
__device__ __half g_He[SLOTS * H_DIM];               // expert hidden  134MB
__device__ float  g_Y[SLOTS * D_DIM];                // expert output   67MB
__device__ int    g_expIdx[SLOTS];
__device__ float  g_expW[SLOTS];
__device__ int    g_counts[E_NUM];
__device__ int    g_fillpos[E_NUM];
__device__ int    g_perm[SLOTS];
__device__ int    g_tileExpert[MAX_TILES];
__device__ int    g_tilePos[MAX_TILES];
__device__ int    g_tileEnd[MAX_TILES];
__device__ int    g_nTiles;

__device__ __forceinline__ float gelu_exact(float x) {
    return 0.5f * x * (1.0f + erff(x * 0.7071067811865476f));
}

__device__ __forceinline__ uint32_t smem_to_u32(const void* p) {
    uint32_t a;
    asm("{ .reg .u64 t; cvta.to.shared.u64 t, %1; cvt.u32.u64 %0, t; }" : "=r"(a) : "l"(p));
    return a;
}
#define CP_ASYNC16(dst, src, sz) \
    asm volatile("cp.async.cg.shared.global [%0], [%1], 16, %2;" \
                 :: "r"(dst), "l"(src), "r"(sz))
#define CP_COMMIT() asm volatile("cp.async.commit_group;" ::: "memory")
#define CP_WAIT2()  asm volatile("cp.async.wait_group 2;" ::: "memory")

// ---------------- misc small kernels ---------------------------------------
__global__ void zero_counts_kernel() {
    if (threadIdx.x < E_NUM) g_counts[threadIdx.x] = 0;
}

// x -> [xh | xh | xl]  (row stride 3072)
__global__ void xsplit_kernel(const float* __restrict__ x) {
    int i = blockIdx.x * blockDim.x + threadIdx.x;    // over T*D/4
    int t = i >> 8;                                   // D/4 = 256
    int c4 = (i & 255) * 4;
    float4 v = reinterpret_cast<const float4*>(x)[i];
    __half h[4], l[4];
    float vv[4] = {v.x, v.y, v.z, v.w};
#pragma unroll
    for (int q = 0; q < 4; q++) {
        h[q] = __float2half_rn(vv[q]);
        l[q] = __float2half_rn(vv[q] - __half2float(h[q]));
    }
    __half* row = g_xsplit + (size_t)t * KR_DIM + c4;
    __half2 h01 = __halves2half2(h[0], h[1]), h23 = __halves2half2(h[2], h[3]);
    __half2 l01 = __halves2half2(l[0], l[1]), l23 = __halves2half2(l[2], l[3]);
    ((__half2*)(row))[0] = h01;        ((__half2*)(row))[1] = h23;
    ((__half2*)(row + 1024))[0] = h01; ((__half2*)(row + 1024))[1] = h23;
    ((__half2*)(row + 2048))[0] = l01; ((__half2*)(row + 2048))[1] = l23;
}

// Wr1*32 -> [wh | wl | wh]  (row stride 3072)
__global__ void wsplit_kernel(const float* __restrict__ w) {
    int i = blockIdx.x * blockDim.x + threadIdx.x;    // over R*D/4
    int r = i >> 8;
    int c4 = (i & 255) * 4;
    float4 v = reinterpret_cast<const float4*>(w)[i];
    float vv[4] = {v.x * 32.f, v.y * 32.f, v.z * 32.f, v.w * 32.f};
    __half h[4], l[4];
#pragma unroll
    for (int q = 0; q < 4; q++) {
        h[q] = __float2half_rn(vv[q]);
        l[q] = __float2half_rn(vv[q] - __half2float(h[q]));
    }
    __half* row = g_wr1split + (size_t)r * KR_DIM + c4;
    __half2 h01 = __halves2half2(h[0], h[1]), h23 = __halves2half2(h[2], h[3]);
    __half2 l01 = __halves2half2(l[0], l[1]), l23 = __halves2half2(l[2], l[3]);
    ((__half2*)(row))[0] = h01;        ((__half2*)(row))[1] = h23;
    ((__half2*)(row + 1024))[0] = l01; ((__half2*)(row + 1024))[1] = l23;
    ((__half2*)(row + 2048))[0] = h01; ((__half2*)(row + 2048))[1] = h23;
}

// fp32 -> fp16 conversion (4 elems/thread). tag: 1=W1, 2=W2
__global__ void f2h_kernel(const float* __restrict__ src, int n4, int tag) {
    int i = blockIdx.x * blockDim.x + threadIdx.x;
    if (i >= n4) return;
    __half* dst = (tag == 1) ? g_W1h : g_W2h;
    float4 v = reinterpret_cast<const float4*>(src)[i];
    __half2* d2 = reinterpret_cast<__half2*>(dst + (size_t)i * 4);
    d2[0] = __floats2half2_rn(v.x, v.y);
    d2[1] = __floats2half2_rn(v.z, v.w);
}

// ---------------- unified HMMA GEMM -----------------------------------------
// MODE 0: router  h = gelu((1/32)*A'B'^T + br1) -> g_hrouter fp32, M dense
// MODE 1: UP      He = gelu(xh@W1[e]^T + b1[e]) fp16, gathered (token=slot>>1)
// MODE 2: DOWN    Y  = He@W2[e]^T + b2[e] fp32, gathered (slot)
// Tile M=128, N=256, K-chunk 64 (128B rows), 4-stage cp.async, 512 threads.
// Mainloop: ONE barrier/iter; loads for it+3 issued before compute(it).
#define OFF_SLOT   0
#define OFF_STAGE  1024
#define STAGE_BYTES 49152           // A 16KB + B 32KB
#define NSTAGE 4
#define SMEM_TOTAL (OFF_STAGE + NSTAGE * STAGE_BYTES)

template <int MODE>
__global__ void __launch_bounds__(512, 1) moe_gemm_kernel(const float* __restrict__ bias_in)
{
    constexpr int K_DIM = (MODE == 0) ? KR_DIM : (MODE == 1 ? 1024 : 4096);
    constexpr int A_STRIDE = (MODE == 2) ? 4096 : KR_DIM;
    constexpr int NITER = K_DIM / 64;

    extern __shared__ char smem[];
    const uint32_t sb = smem_to_u32(smem);
    int* sSlot = (int*)(smem + OFF_SLOT);
    const int tid = threadIdx.x;
    const int wid = tid >> 5;
    const int lane = tid & 31;
    const int n0 = blockIdx.x * 256;

    int m0 = 0, eIdx = 0;
    if (MODE == 0) {
        m0 = blockIdx.y * 128;
    } else {
        int mt = blockIdx.y;
        if (mt >= g_nTiles) return;
        eIdx = g_tileExpert[mt];
        int pos0 = g_tilePos[mt], segEnd = g_tileEnd[mt];
        if (tid < 128) {
            int p = pos0 + tid;
            sSlot[tid] = (p < segEnd) ? g_perm[p] : -1;
        }
    }
    __syncthreads();

    const __half* Abase = (MODE == 2) ? g_He : g_xsplit;
    const __half* Bbase;
    const float* bptr;
    if (MODE == 0)      { Bbase = g_wr1split;                              bptr = bias_in; }
    else if (MODE == 1) { Bbase = g_W1h + (size_t)eIdx * (H_DIM * D_DIM);  bptr = bias_in + eIdx * H_DIM; }
    else                { Bbase = g_W2h + (size_t)eIdx * (D_DIM * H_DIM);  bptr = bias_in + eIdx * D_DIM; }

    // Per-thread A-gather row (resolved once)
    int aRow[2];
    uint32_t aSz[2];
#pragma unroll
    for (int j = 0; j < 2; j++) {
        int r = (tid + j * 512) >> 3;
        aSz[j] = 16;
        if (MODE == 0) aRow[j] = m0 + r;
        else {
            int slot = sSlot[r];
            if (slot < 0) { aRow[j] = 0; aSz[j] = 0; }
            else aRow[j] = (MODE == 1) ? (slot >> 1) : slot;
        }
    }

    // ---- stage loader (A: 128x128B gathered; B: 256x128B) ----
    auto load_stage = [&](int it) {
        const uint32_t so = sb + OFF_STAGE + (uint32_t)(it & 3) * STAGE_BYTES;
        const int kb = it * 128;  // bytes along K
#pragma unroll
        for (int j = 0; j < 2; j++) {
            int c = tid + j * 512;          // 0..1023
            int r = c >> 3;                 // 0..127
            int kc = (c & 7) << 4;          // 0..112
            uint32_t dst = so + (uint32_t)(r * 128 + (kc ^ ((r & 7) << 4)));
            const char* src = (const char*)(Abase + (size_t)aRow[j] * A_STRIDE) + kb + kc;
            CP_ASYNC16(dst, src, aSz[j]);
        }
#pragma unroll
        for (int j = 0; j < 4; j++) {
            int c = tid + j * 512;          // 0..2047
            int r = c >> 3;                 // 0..255
            int kc = (c & 7) << 4;
            uint32_t dst = so + 16384u + (uint32_t)(r * 128 + (kc ^ ((r & 7) << 4)));
            const char* src = (const char*)(Bbase + (size_t)(n0 + r) * K_DIM) + kb + kc;
            CP_ASYNC16(dst, src, 16u);
        }
    };

    // warp grid: 4 (M) x 4 (N); warp tile 32x64
    const int wm = (wid & 3) * 32;
    const int wn = (wid >> 2) * 64;

    float acc[2][8][4];
#pragma unroll
    for (int i = 0; i < 2; i++)
#pragma unroll
        for (int j = 0; j < 8; j++)
#pragma unroll
            for (int k = 0; k < 4; k++) acc[i][j][k] = 0.f;

    // prologue: fill 3 stages (zero-fill padded A rows in all 4 buffers once)
    if (MODE != 0) {
#pragma unroll
        for (int j = 0; j < 2; j++) {
            if (aSz[j] == 0) {
                int c = tid + j * 512;
                int r = c >> 3;
                int kc = (c & 7) << 4;
                uint32_t off = (uint32_t)(r * 128 + (kc ^ ((r & 7) << 4)));
#pragma unroll
                for (int s = 0; s < 4; s++)
                    *(uint4*)(smem + OFF_STAGE + s * STAGE_BYTES + off) =
                        make_uint4(0u, 0u, 0u, 0u);
            }
        }
        __syncthreads();
    }
#pragma unroll
    for (int p = 0; p < 3; p++) {
        load_stage(p);
        CP_COMMIT();
    }

    for (int it = 0; it < NITER; ++it) {
        CP_WAIT2();                   // stage `it` resident (2 groups may remain)
        __syncthreads();              // all warps done with compute(it-1)
        if (it + 3 < NITER) load_stage(it + 3);   // refills buffer (it-1)&3
        CP_COMMIT();                  // keep group count constant

        const uint32_t aOff = sb + OFF_STAGE + (uint32_t)(it & 3) * STAGE_BYTES;
        const uint32_t bOff = aOff + 16384u;

#pragma unroll
        for (int ks = 0; ks < 4; ks++) {
            const int kb32 = ks * 32;
            uint32_t af[2][4];
#pragma unroll
            for (int mf = 0; mf < 2; mf++) {
                int r = wm + mf * 16 + (lane & 15);
                int col = kb32 + ((lane >> 4) << 4);
                uint32_t a = aOff + (uint32_t)(r * 128 + (col ^ ((r & 7) << 4)));
                asm volatile(
                    "ldmatrix.sync.aligned.m8n8.x4.shared.b16 {%0,%1,%2,%3}, [%4];"
                    : "=r"(af[mf][0]), "=r"(af[mf][1]), "=r"(af[mf][2]), "=r"(af[mf][3])
                    : "r"(a));
            }
            uint32_t bf[8][2];
#pragma unroll
            for (int np = 0; np < 4; np++) {
                int r = wn + np * 16 + ((lane >> 4) << 3) + (lane & 7);
                int col = kb32 + ((lane >> 3) & 1) * 16;
                uint32_t a = bOff + (uint32_t)(r * 128 + (col ^ ((r & 7) << 4)));
                asm volatile(
                    "ldmatrix.sync.aligned.m8n8.x4.shared.b16 {%0,%1,%2,%3}, [%4];"
                    : "=r"(bf[2 * np][0]), "=r"(bf[2 * np][1]),
                      "=r"(bf[2 * np + 1][0]), "=r"(bf[2 * np + 1][1])
                    : "r"(a));
            }
#pragma unroll
            for (int mf = 0; mf < 2; mf++)
#pragma unroll
                for (int nf = 0; nf < 8; nf++) {
                    asm volatile(
                        "mma.sync.aligned.m16n8k16.row.col.f32.f16.f16.f32 "
                        "{%0,%1,%2,%3}, {%4,%5,%6,%7}, {%8,%9}, {%0,%1,%2,%3};"
                        : "+f"(acc[mf][nf][0]), "+f"(acc[mf][nf][1]),
                          "+f"(acc[mf][nf][2]), "+f"(acc[mf][nf][3])
                        : "r"(af[mf][0]), "r"(af[mf][1]), "r"(af[mf][2]), "r"(af[mf][3]),
                          "r"(bf[nf][0]), "r"(bf[nf][1]));
                }
        }
    }

    // ---- epilogue ----
    const int lr = lane >> 2;
    const int lc = (lane & 3) * 2;
#pragma unroll
    for (int mf = 0; mf < 2; mf++) {
#pragma unroll
        for (int h = 0; h < 2; h++) {
            int rl = wm + mf * 16 + lr + h * 8;
            int orow;
            if (MODE == 0) orow = m0 + rl;
            else {
                int slot = sSlot[rl];
                if (slot < 0) continue;
                orow = slot;
            }
#pragma unroll
            for (int nf = 0; nf < 8; nf++) {
                int col = n0 + wn + nf * 8 + lc;
                float v0 = acc[mf][nf][h * 2 + 0];
                float v1 = acc[mf][nf][h * 2 + 1];
                if (MODE == 0) {
                    v0 = gelu_exact(v0 * 0.03125f + bptr[col]);
                    v1 = gelu_exact(v1 * 0.03125f + bptr[col + 1]);
                    *reinterpret_cast<float2*>(&g_hrouter[(size_t)orow * R_DIM + col]) =
                        make_float2(v0, v1);
                } else if (MODE == 1) {
                    v0 = gelu_exact(v0 + bptr[col]);
                    v1 = gelu_exact(v1 + bptr[col + 1]);
                    *reinterpret_cast<__half2*>(&g_He[(size_t)orow * H_DIM + col]) =
                        __floats2half2_rn(v0, v1);
                } else {
                    *reinterpret_cast<float2*>(&g_Y[(size_t)orow * D_DIM + col]) =
                        make_float2(v0 + bptr[col], v1 + bptr[col + 1]);
                }
            }
        }
    }
}

// ---------------- router stage 2: logits, softmax, top-2 -------------------
__global__ void router_topk_kernel(const float* __restrict__ Wr2,  // [8,512]
                                   const float* __restrict__ br2)  // [8]
{
    int warp = threadIdx.x >> 5;
    int lane = threadIdx.x & 31;
    int t = blockIdx.x * 8 + warp;
    const float* h = g_hrouter + (size_t)t * R_DIM;

    float acc[E_NUM];
#pragma unroll
    for (int e = 0; e < E_NUM; e++) acc[e] = 0.f;
#pragma unroll
    for (int j = 0; j < 16; j++) {
        int i = lane + 32 * j;
        float hv = h[i];
#pragma unroll
        for (int e = 0; e < E_NUM; e++) acc[e] += hv * Wr2[e * R_DIM + i];
    }
#pragma unroll
    for (int off = 16; off > 0; off >>= 1)
#pragma unroll
        for (int e = 0; e < E_NUM; e++)
            acc[e] += __shfl_xor_sync(0xffffffffu, acc[e], off);

    if (lane == 0) {
        float l[E_NUM];
#pragma unroll
        for (int e = 0; e < E_NUM; e++) l[e] = acc[e] + br2[e];
        int i0 = 0; float v0 = l[0];
#pragma unroll
        for (int e = 1; e < E_NUM; e++) if (l[e] > v0) { v0 = l[e]; i0 = e; }
        int i1 = -1; float v1 = -1e30f;
#pragma unroll
        for (int e = 0; e < E_NUM; e++) if (e != i0 && l[e] > v1) { v1 = l[e]; i1 = e; }
        float m = v0;
        float s = 0.f;
#pragma unroll
        for (int e = 0; e < E_NUM; e++) s += expf(l[e] - m);
        float w0 = expf(v0 - m) / s;
        float w1 = expf(v1 - m) / s;
        g_expIdx[2 * t] = i0;     g_expIdx[2 * t + 1] = i1;
        g_expW[2 * t] = w0;       g_expW[2 * t + 1] = w1;
        atomicAdd(&g_counts[i0], 1);
        atomicAdd(&g_counts[i1], 1);
    }
}

// ---------------- scan + tile map (single thread) ---------------------------
__global__ void scan_kernel() {
    int off = 0, nt = 0;
    for (int e = 0; e < E_NUM; e++) {
        int cnt = g_counts[e];
        g_fillpos[e] = off;
        int tiles = (cnt + 127) >> 7;
        for (int j = 0; j < tiles; j++) {
            g_tileExpert[nt] = e;
            g_tilePos[nt] = off + j * 128;
            g_tileEnd[nt] = off + cnt;
            nt++;
        }
        off += cnt;
    }
    g_nTiles = nt;
}

__global__ void fill_kernel() {
    int s = blockIdx.x * blockDim.x + threadIdx.x;
    if (s >= SLOTS) return;
    int e = g_expIdx[s];
    int pos = atomicAdd(&g_fillpos[e], 1);
    g_perm[pos] = s;
}

// ---------------- combine: out = w0*Y[2t] + w1*Y[2t+1] ---------------------
__global__ void combine_kernel(float* __restrict__ out) {
    int i = blockIdx.x * blockDim.x + threadIdx.x;  // over T*D/4
    int t = i >> 8;
    int c = i & 255;
    float w0 = g_expW[2 * t];
    float w1 = g_expW[2 * t + 1];
    const float4* Y4 = reinterpret_cast<const float4*>(g_Y);
    float4 y0 = Y4[(size_t)(2 * t) * 256 + c];
    float4 y1 = Y4[(size_t)(2 * t + 1) * 256 + c];
    float4 r;
    r.x = w0 * y0.x + w1 * y1.x;
    r.y = w0 * y0.y + w1 * y1.y;
    r.z = w0 * y0.z + w1 * y1.z;
    r.w = w0 * y0.w + w1 * y1.w;
    reinterpret_cast<float4*>(out)[i] = r;
}

// ---------------- launch ----------------------------------------------------
extern "C" void kernel_launch(void* const* d_in, const int* in_sizes, int n_in,
                              void* d_out, int out_size) {
    const float* x   = (const float*)d_in[0];
    const float* Wr1 = (const float*)d_in[1];
    const float* br1 = (const float*)d_in[2];
    const float* Wr2 = (const float*)d_in[3];
    const float* br2 = (const float*)d_in[4];
    const float* W1  = (const float*)d_in[5];
    const float* b1  = (const float*)d_in[6];
    const float* W2  = (const float*)d_in[7];
    const float* b2  = (const float*)d_in[8];
    float* out = (float*)d_out;

    // One-time stream/event setup (no device memory; identical work each call)
    static cudaStream_t sW = nullptr;
    static cudaEvent_t evFork = nullptr, evW = nullptr;
    if (sW == nullptr) {
        cudaStreamCreateWithFlags(&sW, cudaStreamNonBlocking);
        cudaEventCreateWithFlags(&evFork, cudaEventDisableTiming);
        cudaEventCreateWithFlags(&evW, cudaEventDisableTiming);
        cudaFuncSetAttribute(moe_gemm_kernel<0>, cudaFuncAttributeMaxDynamicSharedMemorySize, SMEM_TOTAL);
        cudaFuncSetAttribute(moe_gemm_kernel<1>, cudaFuncAttributeMaxDynamicSharedMemorySize, SMEM_TOTAL);
        cudaFuncSetAttribute(moe_gemm_kernel<2>, cudaFuncAttributeMaxDynamicSharedMemorySize, SMEM_TOTAL);
    }

    zero_counts_kernel<<<1, 32>>>();

    // Fork: weight conversions run concurrently with the router chain
    cudaEventRecord(evFork, 0);
    cudaStreamWaitEvent(sW, evFork, 0);
    {
        int n4 = E_NUM * H_DIM * D_DIM / 4;
        f2h_kernel<<<n4 / 256, 256, 0, sW>>>(W1, n4, 1);
        f2h_kernel<<<n4 / 256, 256, 0, sW>>>(W2, n4, 2);
    }
    cudaEventRecord(evW, sW);

    // Router chain on the main stream
    xsplit_kernel<<<(T_TOKENS * D_DIM / 4) / 256, 256>>>(x);
    wsplit_kernel<<<(R_DIM * D_DIM / 4) / 256, 256>>>(Wr1);
    moe_gemm_kernel<0><<<dim3(2, 64), 512, SMEM_TOTAL>>>(br1);
    router_topk_kernel<<<T_TOKENS / 8, 256>>>(Wr2, br2);
    scan_kernel<<<1, 1>>>();
    fill_kernel<<<SLOTS / 256, 256>>>();

    // Join: expert GEMMs need converted weights + routing
    cudaStreamWaitEvent(0, evW, 0);
    moe_gemm_kernel<1><<<dim3(H_DIM / 256, MAX_TILES), 512, SMEM_TOTAL>>>(b1);
    moe_gemm_kernel<2><<<dim3(D_DIM / 256, MAX_TILES), 512, SMEM_TOTAL>>>(b2);

    combine_kernel<<<T_TOKENS * D_DIM / 4 / 256, 256>>>(out);
}